// round 13
// baseline (speedup 1.0000x reference)
#include <cuda_runtime.h>
#include <cuda_fp16.h>
#include <cstdint>
#include <math.h>

// Problem constants
#define Nn   16384
#define Ee   65536
#define Gg   64
#define INF  63
#define K1   64            // layer-1 K padded 63 -> 64
#define HID  2048
#define MIDD 1024
#define NCLS 18
#define SLOPE 0.01f
#define EPS   1e-5f

// ---------------- scratch (device globals; no allocation allowed) ----------------
__device__ __half g_nmh[(size_t)Nn * HID];   // neighbor sum (half2 atomic target)
__device__ __half g_xh[(size_t)Nn * HID];    // activations (half)
__device__ __half g_h16[(size_t)Nn * K1];    // padded input features (half)
__device__ __half g_yh[(size_t)Nn * HID];    // GEMM output (half)
__device__ float  g_deg[Nn];
__device__ float  g_scale[HID];
__device__ float  g_shift[HID];
__device__ float  g_colsum[HID];
__device__ float  g_colsq[HID];
__device__ float  g_hg[Gg * HID];
__device__ float  g_cnt[Gg];
__device__ float  g_t1[Gg * HID];
__device__ float  g_t2[Gg * MIDD];
// transposed fp16 weights [N=2048 rows, K cols]
__device__ __half g_wh1s[(size_t)HID * K1];
__device__ __half g_wh1n[(size_t)HID * K1];
__device__ __half g_wh2s[(size_t)HID * HID];
__device__ __half g_wh2n[(size_t)HID * HID];
__device__ __half g_wh3s[(size_t)HID * HID];
__device__ __half g_wh3n[(size_t)HID * HID];

// ==================== helpers ====================
__device__ __forceinline__ uint32_t smem_u32(const void* p) {
    uint32_t a;
    asm("{ .reg .u64 t; cvta.to.shared.u64 t, %1; cvt.u32.u64 %0, t; }" : "=r"(a) : "l"(p));
    return a;
}
__device__ __forceinline__ void cp_async16(uint32_t dst, const void* src) {
    asm volatile("cp.async.cg.shared.global [%0], [%1], 16;" :: "r"(dst), "l"(src) : "memory");
}
__device__ __forceinline__ void cp_commit() {
    asm volatile("cp.async.commit_group;" ::: "memory");
}
__device__ __forceinline__ void mma_f16(float* d, const uint32_t* a, const uint32_t* b) {
    asm volatile(
        "mma.sync.aligned.m16n8k16.row.col.f32.f16.f16.f32 "
        "{%0,%1,%2,%3}, {%4,%5,%6,%7}, {%8,%9}, {%0,%1,%2,%3};"
        : "+f"(d[0]), "+f"(d[1]), "+f"(d[2]), "+f"(d[3])
        : "r"(a[0]), "r"(a[1]), "r"(a[2]), "r"(a[3]), "r"(b[0]), "r"(b[1]));
}
#define LDSM_X4(r0, r1, r2, r3, addr) \
    asm volatile("ldmatrix.sync.aligned.m8n8.x4.shared.b16 {%0,%1,%2,%3}, [%4];" \
        : "=r"(r0), "=r"(r1), "=r"(r2), "=r"(r3) : "r"(addr))

// ==================== fp16 mma.sync dual-source GEMM (ldmatrix mainloop) ====================
// acc = (Anb@Bnb^T) * (1/max(deg,1)) [row-wise] + Aself@Bself^T + bias
// Output C is fp16 [_, HID]; BN column sum/sumsq accumulated in fp32.
#define PADW 36
#define ROWB 144
#define OPB  (128 * ROWB)
#define STAGE_BYTES (2 * OPB)
#define NSTAGE 3
#define TCG_SMEM_BYTES (NSTAGE * STAGE_BYTES)    // 110592 B
#define KCH 64

template<int K>
__device__ __forceinline__ void tcg_issue_chunk(uint32_t sb, int stage, int tid,
                                                const __half* A, const __half* B,
                                                int rowBlk, int colBlk, int k0) {
    uint32_t base = sb + (uint32_t)stage * STAGE_BYTES;
    #pragma unroll
    for (int i = 0; i < 4; i++) {
        int t = tid + i * 256;
        int r = t >> 3, sg = t & 7;
        uint32_t off = (uint32_t)r * ROWB + (uint32_t)sg * 16;
        cp_async16(base + off, A + (size_t)(rowBlk + r) * K + k0 + sg * 8);
        cp_async16(base + OPB + off, B + (size_t)(colBlk + r) * K + k0 + sg * 8);
    }
}

template<int K>
__global__ void __launch_bounds__(256, 2)
tc_gemm_dual(const __half* __restrict__ Anb, const __half* __restrict__ Bnb,
             const __half* __restrict__ Aself, const __half* __restrict__ Bself,
             const float* __restrict__ bias, const float* __restrict__ deg,
             __half* __restrict__ C,
             float* __restrict__ colsum, float* __restrict__ colsq) {
    extern __shared__ __align__(16) float smem[];
    uint32_t sb = smem_u32(smem);
    const int tid  = threadIdx.x;
    const int wid  = tid >> 5;
    const int lane = tid & 31;
    const int rowBlk = blockIdx.y * 128;
    const int colBlk = blockIdx.x * 128;
    const int wm = (wid & 1) * 64;
    const int wn = (wid >> 1) * 32;
    const int lr = lane >> 2;
    const int lc = lane & 3;

    // ldmatrix lane-address components (within a tile): 16-row group layout
    const uint32_t lmRow  = (uint32_t)((lane & 7) + ((lane >> 3) & 1) * 8) * ROWB
                          + (uint32_t)((lane >> 4) & 1) * 16;

    float acc[4][4][4];
    #pragma unroll
    for (int i = 0; i < 4; i++)
        #pragma unroll
        for (int j = 0; j < 4; j++)
            #pragma unroll
            for (int k = 0; k < 4; k++) acc[i][j][k] = 0.0f;

    constexpr int NC  = K / KCH;
    constexpr int TOT = 2 * NC;

    tcg_issue_chunk<K>(sb, 0, tid, Anb, Bnb, rowBlk, colBlk, 0);
    cp_commit();
    {
        const __half* A = (1 < NC) ? Anb : Aself;
        const __half* B = (1 < NC) ? Bnb : Bself;
        int k0 = (1 < NC) ? KCH : 0;
        tcg_issue_chunk<K>(sb, 1, tid, A, B, rowBlk, colBlk, k0);
        cp_commit();
    }

    int sc = 0;
    for (int c = 0; c < TOT; c++) {
        int n2 = c + 2;
        if (n2 < TOT) {
            const __half* A = (n2 < NC) ? Anb : Aself;
            const __half* B = (n2 < NC) ? Bnb : Bself;
            int k0 = (n2 & (NC - 1)) * KCH;
            int ps = sc + 2; if (ps >= NSTAGE) ps -= NSTAGE;
            tcg_issue_chunk<K>(sb, ps, tid, A, B, rowBlk, colBlk, k0);
        }
        cp_commit();
        asm volatile("cp.async.wait_group 2;" ::: "memory");
        __syncthreads();

        uint32_t aBase = sb + (uint32_t)sc * STAGE_BYTES + (uint32_t)wm * ROWB + lmRow;
        uint32_t bBase = sb + (uint32_t)sc * STAGE_BYTES + OPB + (uint32_t)wn * ROWB + lmRow;

        #pragma unroll
        for (int kp = 0; kp < KCH; kp += 16) {
            uint32_t kOff = (uint32_t)kp * 2;
            uint32_t af[4][4], bf[4][2];
            #pragma unroll
            for (int mt = 0; mt < 4; mt++) {
                LDSM_X4(af[mt][0], af[mt][1], af[mt][2], af[mt][3],
                        aBase + (uint32_t)(mt * 16) * ROWB + kOff);
            }
            #pragma unroll
            for (int ntp = 0; ntp < 2; ntp++) {
                LDSM_X4(bf[2 * ntp][0], bf[2 * ntp + 1][0],
                        bf[2 * ntp][1], bf[2 * ntp + 1][1],
                        bBase + (uint32_t)(ntp * 16) * ROWB + kOff);
            }
            #pragma unroll
            for (int mt = 0; mt < 4; mt++)
                #pragma unroll
                for (int nt = 0; nt < 4; nt++)
                    mma_f16(acc[mt][nt], af[mt], bf[nt]);
        }
        __syncthreads();

        // end of neighbor source: scale accumulator rows by 1/max(deg,1)
        if (c == NC - 1) {
            #pragma unroll
            for (int mt = 0; mt < 4; mt++) {
                int gr = rowBlk + wm + mt * 16 + lr;
                float i0 = 1.0f / fmaxf(deg[gr], 1.0f);
                float i1 = 1.0f / fmaxf(deg[gr + 8], 1.0f);
                #pragma unroll
                for (int nt = 0; nt < 4; nt++) {
                    acc[mt][nt][0] *= i0; acc[mt][nt][1] *= i0;
                    acc[mt][nt][2] *= i1; acc[mt][nt][3] *= i1;
                }
            }
        }
        sc++; if (sc >= NSTAGE) sc = 0;
    }

    // epilogue: store fp16 (+bias), accumulate per-column fp32 sum / sumsq
    #pragma unroll
    for (int nt = 0; nt < 4; nt++) {
        int gc = colBlk + wn + nt * 8 + 2 * lc;
        float bv0 = bias[gc], bv1 = bias[gc + 1];
        float s0 = 0.f, s1 = 0.f, q0 = 0.f, q1 = 0.f;
        #pragma unroll
        for (int mt = 0; mt < 4; mt++) {
            int gr = rowBlk + wm + mt * 16 + lr;
            float v00 = acc[mt][nt][0] + bv0;
            float v01 = acc[mt][nt][1] + bv1;
            float v10 = acc[mt][nt][2] + bv0;
            float v11 = acc[mt][nt][3] + bv1;
            *(__half2*)&C[(size_t)gr * HID + gc]       = __floats2half2_rn(v00, v01);
            *(__half2*)&C[(size_t)(gr + 8) * HID + gc] = __floats2half2_rn(v10, v11);
            s0 += v00 + v10;  s1 += v01 + v11;
            q0 += v00 * v00 + v10 * v10;
            q1 += v01 * v01 + v11 * v11;
        }
        #pragma unroll
        for (int st = 4; st <= 16; st <<= 1) {
            s0 += __shfl_xor_sync(0xFFFFFFFF, s0, st);
            s1 += __shfl_xor_sync(0xFFFFFFFF, s1, st);
            q0 += __shfl_xor_sync(0xFFFFFFFF, q0, st);
            q1 += __shfl_xor_sync(0xFFFFFFFF, q1, st);
        }
        if (lr == 0) {
            atomicAdd(&colsum[gc],     s0);
            atomicAdd(&colsum[gc + 1], s1);
            atomicAdd(&colsq[gc],      q0);
            atomicAdd(&colsq[gc + 1],  q1);
        }
    }
}

// colsum/colsq -> scale/shift
__global__ void bn_scale(const float* __restrict__ colsum, const float* __restrict__ colsq,
                         const float* __restrict__ gamma, const float* __restrict__ beta,
                         float* __restrict__ scale, float* __restrict__ shift) {
    int c = blockIdx.x * blockDim.x + threadIdx.x;
    float mu  = colsum[c] / (float)Nn;
    float var = colsq[c] / (float)Nn - mu * mu;
    float sc  = gamma[c] * rsqrtf(var + EPS);
    scale[c] = sc;
    shift[c] = beta[c] - mu * sc;
}

// ==================== weight transposes (+ fp16 convert) ====================
__global__ void transpose_cvt(const float* __restrict__ W, __half* __restrict__ Wt) {
    __shared__ float tile[32][33];
    int n0 = blockIdx.x * 32, k0 = blockIdx.y * 32;
    int tx = threadIdx.x, ty = threadIdx.y;
    #pragma unroll
    for (int j = 0; j < 4; j++)
        tile[ty + j * 8][tx] = W[(size_t)(k0 + ty + j * 8) * HID + (n0 + tx)];
    __syncthreads();
    #pragma unroll
    for (int j = 0; j < 4; j++)
        Wt[(size_t)(n0 + ty + j * 8) * HID + (k0 + tx)] = __float2half_rn(tile[tx][ty + j * 8]);
}

// W1 [63, 2048] -> Wt [2048 rows, 64 cols] (col 63 zero-padded)
__global__ void transpose_cvt1(const float* __restrict__ W, __half* __restrict__ Wt) {
    __shared__ float tile[32][33];
    int n0 = blockIdx.x * 32, k0 = blockIdx.y * 32;
    int tx = threadIdx.x, ty = threadIdx.y;
    #pragma unroll
    for (int j = 0; j < 4; j++) {
        int k = k0 + ty + j * 8;
        tile[ty + j * 8][tx] = (k < INF) ? W[(size_t)k * HID + (n0 + tx)] : 0.0f;
    }
    __syncthreads();
    #pragma unroll
    for (int j = 0; j < 4; j++)
        Wt[(size_t)(n0 + ty + j * 8) * K1 + (k0 + tx)] = __float2half_rn(tile[tx][ty + j * 8]);
}

// h [Nn, 63] fp32 -> h16 [Nn, 64] half (padded)
__global__ void hpad(const float* __restrict__ h, __half* __restrict__ h16) {
    int row = blockIdx.x;
    int c = threadIdx.x;
    h16[(size_t)row * K1 + c] = (c < INF) ? __float2half_rn(h[(size_t)row * INF + c]) : __half(0);
}

// ==================== graph kernels ====================
__global__ void deg_kernel(const int* __restrict__ dst, float* __restrict__ deg) {
    int i = blockIdx.x * blockDim.x + threadIdx.x;
    if (i < Ee) atomicAdd(&deg[dst[i]], 1.0f);
}

// half2 atomic scatter: out[dst[e], :] += x[src[e], :]
__global__ void scatter_add_h2(const __half* __restrict__ xh, const int* __restrict__ src,
                               const int* __restrict__ dst, __half* __restrict__ out, int F) {
    int e = blockIdx.x;
    int f2 = blockIdx.y * blockDim.x + threadIdx.x;
    if (f2 * 2 >= F) return;
    int s = src[e], d = dst[e];
    __half2 v = *((const __half2*)(xh + (size_t)s * F) + f2);
    atomicAdd((__half2*)(out + (size_t)d * F) + f2, v);
}

// BN apply + leaky relu: half in (y), half out (x).  grid: (HID/4/256, Nn)
__global__ void bn_apply_h(const __half* __restrict__ Y, __half* __restrict__ Xh,
                           const float* __restrict__ scale, const float* __restrict__ shift) {
    int row = blockIdx.y;
    int f4 = blockIdx.x * blockDim.x + threadIdx.x;
    const __half2* yp = (const __half2*)(Y + (size_t)row * HID) + f4 * 2;
    float2 a = __half22float2(yp[0]);
    float2 b = __half22float2(yp[1]);
    float4 sc = *((const float4*)scale + f4);
    float4 sh = *((const float4*)shift + f4);
    float vx = a.x * sc.x + sh.x; vx = (vx > 0.f) ? vx : SLOPE * vx;
    float vy = a.y * sc.y + sh.y; vy = (vy > 0.f) ? vy : SLOPE * vy;
    float vz = b.x * sc.z + sh.z; vz = (vz > 0.f) ? vz : SLOPE * vz;
    float vw = b.y * sc.w + sh.w; vw = (vw > 0.f) ? vw : SLOPE * vw;
    __half2* xp = (__half2*)(Xh + (size_t)row * HID) + f4 * 2;
    xp[0] = __floats2half2_rn(vx, vy);
    xp[1] = __floats2half2_rn(vz, vw);
}

// layer-3: BN apply + leaky relu + pooled atomic accumulate (half in, fp32 pool)
__global__ void bn_apply_pool(const __half* __restrict__ Y, const int* __restrict__ gid,
                              const float* __restrict__ scale, const float* __restrict__ shift,
                              float* __restrict__ hg) {
    int row = blockIdx.y;
    int f4 = blockIdx.x * blockDim.x + threadIdx.x;
    const __half2* yp = (const __half2*)(Y + (size_t)row * HID) + f4 * 2;
    float2 a = __half22float2(yp[0]);
    float2 b = __half22float2(yp[1]);
    float4 sc = *((const float4*)scale + f4);
    float4 sh = *((const float4*)shift + f4);
    float vx = a.x * sc.x + sh.x; vx = (vx > 0.f) ? vx : SLOPE * vx;
    float vy = a.y * sc.y + sh.y; vy = (vy > 0.f) ? vy : SLOPE * vy;
    float vz = b.x * sc.z + sh.z; vz = (vz > 0.f) ? vz : SLOPE * vz;
    float vw = b.y * sc.w + sh.w; vw = (vw > 0.f) ? vw : SLOPE * vw;
    int g = gid[row];
    float* dst = hg + (size_t)g * HID + f4 * 4;
    atomicAdd(dst,     vx);
    atomicAdd(dst + 1, vy);
    atomicAdd(dst + 2, vz);
    atomicAdd(dst + 3, vw);
}

// ---------------- pooling tail (fp32) ----------------
__global__ void cnt_kernel(const int* __restrict__ gid, float* __restrict__ cnt) {
    int i = blockIdx.x * blockDim.x + threadIdx.x;
    if (i < Nn) atomicAdd(&cnt[gid[i]], 1.0f);
}

__global__ void hg_div(float* __restrict__ hg, const float* __restrict__ cnt, int C) {
    int g = blockIdx.y;
    int c = blockIdx.x * blockDim.x + threadIdx.x;
    if (c >= C) return;
    hg[(size_t)g * C + c] *= 1.0f / fmaxf(cnt[g], 1.0f);
}

// ---------------- fp32 scalar MLP head (proven low-error path) ----------------
__global__ void head_gemm(const float* __restrict__ X, const float* __restrict__ W,
                          const float* __restrict__ b, float* __restrict__ Y,
                          int K, int Nc, int do_lrelu) {
    extern __shared__ float xs[];
    int r = blockIdx.y;
    for (int i = threadIdx.x; i < K; i += blockDim.x) xs[i] = X[(size_t)r * K + i];
    __syncthreads();
    int c = blockIdx.x * blockDim.x + threadIdx.x;
    if (c >= Nc) return;
    float acc = 0.0f;
    int k = 0;
    for (; k + 4 <= K; k += 4) {
        acc += xs[k    ] * W[(size_t)(k    ) * Nc + c];
        acc += xs[k + 1] * W[(size_t)(k + 1) * Nc + c];
        acc += xs[k + 2] * W[(size_t)(k + 2) * Nc + c];
        acc += xs[k + 3] * W[(size_t)(k + 3) * Nc + c];
    }
    for (; k < K; k++) acc += xs[k] * W[(size_t)k * Nc + c];
    acc += b[c];
    if (do_lrelu) acc = (acc > 0.0f) ? acc : SLOPE * acc;
    Y[(size_t)r * Nc + c] = acc;
}

// ==================== launch ====================
extern "C" void kernel_launch(void* const* d_in, const int* in_sizes, int n_in,
                              void* d_out, int out_size) {
    (void)in_sizes; (void)n_in; (void)out_size;
    const float* h     = (const float*)d_in[0];
    const int*   src   = (const int*)  d_in[1];
    const int*   dst   = (const int*)  d_in[2];
    const int*   gid   = (const int*)  d_in[3];
    const float* Ws1   = (const float*)d_in[4];
    const float* Wn1   = (const float*)d_in[5];
    const float* b1    = (const float*)d_in[6];
    const float* Ws2   = (const float*)d_in[7];
    const float* Wn2   = (const float*)d_in[8];
    const float* b2    = (const float*)d_in[9];
    const float* Ws3   = (const float*)d_in[10];
    const float* Wn3   = (const float*)d_in[11];
    const float* b3    = (const float*)d_in[12];
    const float* g1    = (const float*)d_in[13];
    const float* be1   = (const float*)d_in[14];
    const float* g2    = (const float*)d_in[15];
    const float* be2   = (const float*)d_in[16];
    const float* g3    = (const float*)d_in[17];
    const float* be3   = (const float*)d_in[18];
    const float* fc1_w = (const float*)d_in[19];
    const float* fc1_b = (const float*)d_in[20];
    const float* fc2_w = (const float*)d_in[21];
    const float* fc2_b = (const float*)d_in[22];
    const float* fc3_w = (const float*)d_in[23];
    const float* fc3_b = (const float*)d_in[24];
    float* out = (float*)d_out;

    float *deg, *scale, *shift, *colsum, *colsq, *hg, *cnt, *t1, *t2;
    __half *nmh, *xh, *h16, *yh;
    __half *wh1s, *wh1n, *wh2s, *wh2n, *wh3s, *wh3n;
    cudaGetSymbolAddress((void**)&nmh,    g_nmh);
    cudaGetSymbolAddress((void**)&xh,     g_xh);
    cudaGetSymbolAddress((void**)&h16,    g_h16);
    cudaGetSymbolAddress((void**)&yh,     g_yh);
    cudaGetSymbolAddress((void**)&deg,    g_deg);
    cudaGetSymbolAddress((void**)&scale,  g_scale);
    cudaGetSymbolAddress((void**)&shift,  g_shift);
    cudaGetSymbolAddress((void**)&colsum, g_colsum);
    cudaGetSymbolAddress((void**)&colsq,  g_colsq);
    cudaGetSymbolAddress((void**)&hg,     g_hg);
    cudaGetSymbolAddress((void**)&cnt,    g_cnt);
    cudaGetSymbolAddress((void**)&t1,     g_t1);
    cudaGetSymbolAddress((void**)&t2,     g_t2);
    cudaGetSymbolAddress((void**)&wh1s,   g_wh1s);
    cudaGetSymbolAddress((void**)&wh1n,   g_wh1n);
    cudaGetSymbolAddress((void**)&wh2s,   g_wh2s);
    cudaGetSymbolAddress((void**)&wh2n,   g_wh2n);
    cudaGetSymbolAddress((void**)&wh3s,   g_wh3s);
    cudaGetSymbolAddress((void**)&wh3n,   g_wh3n);

    cudaFuncSetAttribute(tc_gemm_dual<K1>,  cudaFuncAttributeMaxDynamicSharedMemorySize, TCG_SMEM_BYTES);
    cudaFuncSetAttribute(tc_gemm_dual<HID>, cudaFuncAttributeMaxDynamicSharedMemorySize, TCG_SMEM_BYTES);

    cudaStream_t s = 0;

    // weight transposes (+ fp16 convert), input pad
    dim3 tblk(32, 8);
    transpose_cvt1<<<dim3(HID / 32, K1 / 32), tblk, 0, s>>>(Ws1, wh1s);
    transpose_cvt1<<<dim3(HID / 32, K1 / 32), tblk, 0, s>>>(Wn1, wh1n);
    transpose_cvt<<<dim3(HID / 32, HID / 32), tblk, 0, s>>>(Ws2, wh2s);
    transpose_cvt<<<dim3(HID / 32, HID / 32), tblk, 0, s>>>(Wn2, wh2n);
    transpose_cvt<<<dim3(HID / 32, HID / 32), tblk, 0, s>>>(Ws3, wh3s);
    transpose_cvt<<<dim3(HID / 32, HID / 32), tblk, 0, s>>>(Wn3, wh3n);
    hpad<<<Nn, K1, 0, s>>>(h, h16);

    // degrees
    cudaMemsetAsync(deg, 0, Nn * sizeof(float), s);
    deg_kernel<<<Ee / 256, 256, 0, s>>>(dst, deg);

    dim3 tc_grid(HID / 128, Nn / 128);
    dim3 ew4_grid(HID / 4 / 256, Nn);

    // ---- Layer 1 (K = 64, tensor GEMM, fused BN stats + deg-fold) ----
    cudaMemsetAsync(nmh, 0, (size_t)Nn * K1 * sizeof(__half), s);
    scatter_add_h2<<<dim3(Ee, 1), 32, 0, s>>>(h16, src, dst, nmh, K1);
    cudaMemsetAsync(colsum, 0, HID * sizeof(float), s);
    cudaMemsetAsync(colsq,  0, HID * sizeof(float), s);
    tc_gemm_dual<K1><<<tc_grid, 256, TCG_SMEM_BYTES, s>>>(nmh, wh1n, h16, wh1s, b1, deg, yh,
                                                          colsum, colsq);
    bn_scale<<<HID / 256, 256, 0, s>>>(colsum, colsq, g1, be1, scale, shift);
    bn_apply_h<<<ew4_grid, 256, 0, s>>>(yh, xh, scale, shift);

    // ---- Layer 2 ----
    cudaMemsetAsync(nmh, 0, (size_t)Nn * HID * sizeof(__half), s);
    scatter_add_h2<<<dim3(Ee, HID / 2 / 128), 128, 0, s>>>(xh, src, dst, nmh, HID);
    cudaMemsetAsync(colsum, 0, HID * sizeof(float), s);
    cudaMemsetAsync(colsq,  0, HID * sizeof(float), s);
    tc_gemm_dual<HID><<<tc_grid, 256, TCG_SMEM_BYTES, s>>>(nmh, wh2n, xh, wh2s, b2, deg, yh,
                                                           colsum, colsq);
    bn_scale<<<HID / 256, 256, 0, s>>>(colsum, colsq, g2, be2, scale, shift);
    bn_apply_h<<<ew4_grid, 256, 0, s>>>(yh, xh, scale, shift);

    // ---- Layer 3 ----
    cudaMemsetAsync(nmh, 0, (size_t)Nn * HID * sizeof(__half), s);
    scatter_add_h2<<<dim3(Ee, HID / 2 / 128), 128, 0, s>>>(xh, src, dst, nmh, HID);
    cudaMemsetAsync(colsum, 0, HID * sizeof(float), s);
    cudaMemsetAsync(colsq,  0, HID * sizeof(float), s);
    tc_gemm_dual<HID><<<tc_grid, 256, TCG_SMEM_BYTES, s>>>(nmh, wh3n, xh, wh3s, b3, deg, yh,
                                                           colsum, colsq);
    bn_scale<<<HID / 256, 256, 0, s>>>(colsum, colsq, g3, be3, scale, shift);

    // ---- Pooling (fused BN apply, fp32) ----
    cudaMemsetAsync(hg, 0, Gg * HID * sizeof(float), s);
    cudaMemsetAsync(cnt, 0, Gg * sizeof(float), s);
    cnt_kernel<<<Nn / 256, 256, 0, s>>>(gid, cnt);
    bn_apply_pool<<<ew4_grid, 256, 0, s>>>(yh, gid, scale, shift, hg);
    hg_div<<<dim3(HID / 256, Gg), 256, 0, s>>>(hg, cnt, HID);

    // ---- MLP head (fp32 scalar, low-error) ----
    head_gemm<<<dim3((HID + 127) / 128, Gg), 128, HID * sizeof(float), s>>>(
        hg, fc1_w, fc1_b, t1, HID, HID, 1);
    head_gemm<<<dim3((MIDD + 127) / 128, Gg), 128, HID * sizeof(float), s>>>(
        t1, fc2_w, fc2_b, t2, HID, MIDD, 1);
    head_gemm<<<dim3(1, Gg), 128, MIDD * sizeof(float), s>>>(
        t2, fc3_w, fc3_b, out, MIDD, NCLS, 0);
}

// round 15
// speedup vs baseline: 1.0663x; 1.0663x over previous
#include <cuda_runtime.h>
#include <cuda_fp16.h>
#include <cstdint>
#include <math.h>

// Problem constants
#define Nn   16384
#define Ee   65536
#define Gg   64
#define INF  63
#define K1   64            // layer-1 K padded 63 -> 64
#define HID  2048
#define MIDD 1024
#define NCLS 18
#define SLOPE 0.01f
#define EPS   1e-5f

// ---------------- scratch (device globals; no allocation allowed) ----------------
__device__ __half g_nmh[(size_t)Nn * HID];   // neighbor sum (half2 atomic target)
__device__ __half g_xh[(size_t)Nn * HID];    // activations (half)
__device__ __half g_h16[(size_t)Nn * K1];    // padded input features (half)
__device__ __half g_yh[(size_t)Nn * HID];    // GEMM output (half)
__device__ float  g_deg[Nn];
__device__ float  g_scale[HID];
__device__ float  g_shift[HID];
__device__ float  g_colsum[HID];
__device__ float  g_colsq[HID];
__device__ float  g_hg[Gg * HID];
__device__ float  g_cnt[Gg];
__device__ float  g_t1[Gg * HID];
__device__ float  g_t2[Gg * MIDD];
// transposed fp16 weights [N=2048 rows, K cols]
__device__ __half g_wh1s[(size_t)HID * K1];
__device__ __half g_wh1n[(size_t)HID * K1];
__device__ __half g_wh2s[(size_t)HID * HID];
__device__ __half g_wh2n[(size_t)HID * HID];
__device__ __half g_wh3s[(size_t)HID * HID];
__device__ __half g_wh3n[(size_t)HID * HID];

// ==================== helpers ====================
__device__ __forceinline__ uint32_t smem_u32(const void* p) {
    uint32_t a;
    asm("{ .reg .u64 t; cvta.to.shared.u64 t, %1; cvt.u32.u64 %0, t; }" : "=r"(a) : "l"(p));
    return a;
}
__device__ __forceinline__ void cp_async16(uint32_t dst, const void* src) {
    asm volatile("cp.async.cg.shared.global [%0], [%1], 16;" :: "r"(dst), "l"(src) : "memory");
}
__device__ __forceinline__ void cp_commit() {
    asm volatile("cp.async.commit_group;" ::: "memory");
}
__device__ __forceinline__ void mma_f16(float* d, const uint32_t* a, const uint32_t* b) {
    asm volatile(
        "mma.sync.aligned.m16n8k16.row.col.f32.f16.f16.f32 "
        "{%0,%1,%2,%3}, {%4,%5,%6,%7}, {%8,%9}, {%0,%1,%2,%3};"
        : "+f"(d[0]), "+f"(d[1]), "+f"(d[2]), "+f"(d[3])
        : "r"(a[0]), "r"(a[1]), "r"(a[2]), "r"(a[3]), "r"(b[0]), "r"(b[1]));
}

// ==================== fp16 mma.sync dual-source GEMM (LDS mainloop, proven) ====================
// acc = (Anb@Bnb^T) * (1/max(deg,1)) [row-wise] + Aself@Bself^T + bias
// Output C fp16 [_, HID]; BN column sum/sumsq accumulated in fp32.
#define PADW 36
#define ROWB 144
#define OPB  (128 * ROWB)
#define STAGE_BYTES (2 * OPB)
#define NSTAGE 3
#define TCG_SMEM_BYTES (NSTAGE * STAGE_BYTES)    // 110592 B
#define KCH 64

template<int K>
__device__ __forceinline__ void tcg_issue_chunk(uint32_t sb, int stage, int tid,
                                                const __half* A, const __half* B,
                                                int rowBlk, int colBlk, int k0) {
    uint32_t base = sb + (uint32_t)stage * STAGE_BYTES;
    #pragma unroll
    for (int i = 0; i < 4; i++) {
        int t = tid + i * 256;
        int r = t >> 3, sg = t & 7;
        uint32_t off = (uint32_t)r * ROWB + (uint32_t)sg * 16;
        cp_async16(base + off, A + (size_t)(rowBlk + r) * K + k0 + sg * 8);
        cp_async16(base + OPB + off, B + (size_t)(colBlk + r) * K + k0 + sg * 8);
    }
}

template<int K>
__global__ void __launch_bounds__(256, 2)
tc_gemm_dual(const __half* __restrict__ Anb, const __half* __restrict__ Bnb,
             const __half* __restrict__ Aself, const __half* __restrict__ Bself,
             const float* __restrict__ bias, const float* __restrict__ deg,
             __half* __restrict__ C,
             float* __restrict__ colsum, float* __restrict__ colsq) {
    extern __shared__ __align__(16) float smem[];
    uint32_t sb = smem_u32(smem);
    const int tid  = threadIdx.x;
    const int wid  = tid >> 5;
    const int lane = tid & 31;
    const int rowBlk = blockIdx.y * 128;
    const int colBlk = blockIdx.x * 128;
    const int wm = (wid & 1) * 64;
    const int wn = (wid >> 1) * 32;
    const int lr = lane >> 2;
    const int lc = lane & 3;

    float acc[4][4][4];
    #pragma unroll
    for (int i = 0; i < 4; i++)
        #pragma unroll
        for (int j = 0; j < 4; j++)
            #pragma unroll
            for (int k = 0; k < 4; k++) acc[i][j][k] = 0.0f;

    constexpr int NC  = K / KCH;
    constexpr int TOT = 2 * NC;

    tcg_issue_chunk<K>(sb, 0, tid, Anb, Bnb, rowBlk, colBlk, 0);
    cp_commit();
    {
        const __half* A = (1 < NC) ? Anb : Aself;
        const __half* B = (1 < NC) ? Bnb : Bself;
        int k0 = (1 < NC) ? KCH : 0;
        tcg_issue_chunk<K>(sb, 1, tid, A, B, rowBlk, colBlk, k0);
        cp_commit();
    }

    int sc = 0;
    for (int c = 0; c < TOT; c++) {
        int n2 = c + 2;
        if (n2 < TOT) {
            const __half* A = (n2 < NC) ? Anb : Aself;
            const __half* B = (n2 < NC) ? Bnb : Bself;
            int k0 = (n2 & (NC - 1)) * KCH;
            int ps = sc + 2; if (ps >= NSTAGE) ps -= NSTAGE;
            tcg_issue_chunk<K>(sb, ps, tid, A, B, rowBlk, colBlk, k0);
        }
        cp_commit();
        asm volatile("cp.async.wait_group 2;" ::: "memory");
        __syncthreads();

        const uint32_t* As = (const uint32_t*)smem + (size_t)sc * (STAGE_BYTES / 4);
        const uint32_t* Bs = As + OPB / 4;

        #pragma unroll
        for (int kp = 0; kp < KCH; kp += 16) {
            int kw = kp >> 1;
            uint32_t af[4][4], bf[4][2];
            #pragma unroll
            for (int mt = 0; mt < 4; mt++) {
                int r0 = wm + mt * 16 + lr;
                af[mt][0] = As[r0 * PADW + kw + lc];
                af[mt][1] = As[(r0 + 8) * PADW + kw + lc];
                af[mt][2] = As[r0 * PADW + kw + lc + 4];
                af[mt][3] = As[(r0 + 8) * PADW + kw + lc + 4];
            }
            #pragma unroll
            for (int nt = 0; nt < 4; nt++) {
                int n0 = wn + nt * 8 + lr;
                bf[nt][0] = Bs[n0 * PADW + kw + lc];
                bf[nt][1] = Bs[n0 * PADW + kw + lc + 4];
            }
            #pragma unroll
            for (int mt = 0; mt < 4; mt++)
                #pragma unroll
                for (int nt = 0; nt < 4; nt++)
                    mma_f16(acc[mt][nt], af[mt], bf[nt]);
        }
        __syncthreads();

        if (c == NC - 1) {
            #pragma unroll
            for (int mt = 0; mt < 4; mt++) {
                int gr = rowBlk + wm + mt * 16 + lr;
                float i0 = 1.0f / fmaxf(deg[gr], 1.0f);
                float i1 = 1.0f / fmaxf(deg[gr + 8], 1.0f);
                #pragma unroll
                for (int nt = 0; nt < 4; nt++) {
                    acc[mt][nt][0] *= i0; acc[mt][nt][1] *= i0;
                    acc[mt][nt][2] *= i1; acc[mt][nt][3] *= i1;
                }
            }
        }
        sc++; if (sc >= NSTAGE) sc = 0;
    }

    // epilogue: store fp16 (+bias), accumulate per-column fp32 sum / sumsq
    #pragma unroll
    for (int nt = 0; nt < 4; nt++) {
        int gc = colBlk + wn + nt * 8 + 2 * lc;
        float bv0 = bias[gc], bv1 = bias[gc + 1];
        float s0 = 0.f, s1 = 0.f, q0 = 0.f, q1 = 0.f;
        #pragma unroll
        for (int mt = 0; mt < 4; mt++) {
            int gr = rowBlk + wm + mt * 16 + lr;
            float v00 = acc[mt][nt][0] + bv0;
            float v01 = acc[mt][nt][1] + bv1;
            float v10 = acc[mt][nt][2] + bv0;
            float v11 = acc[mt][nt][3] + bv1;
            *(__half2*)&C[(size_t)gr * HID + gc]       = __floats2half2_rn(v00, v01);
            *(__half2*)&C[(size_t)(gr + 8) * HID + gc] = __floats2half2_rn(v10, v11);
            s0 += v00 + v10;  s1 += v01 + v11;
            q0 += v00 * v00 + v10 * v10;
            q1 += v01 * v01 + v11 * v11;
        }
        #pragma unroll
        for (int st = 4; st <= 16; st <<= 1) {
            s0 += __shfl_xor_sync(0xFFFFFFFF, s0, st);
            s1 += __shfl_xor_sync(0xFFFFFFFF, s1, st);
            q0 += __shfl_xor_sync(0xFFFFFFFF, q0, st);
            q1 += __shfl_xor_sync(0xFFFFFFFF, q1, st);
        }
        if (lr == 0) {
            atomicAdd(&colsum[gc],     s0);
            atomicAdd(&colsum[gc + 1], s1);
            atomicAdd(&colsq[gc],      q0);
            atomicAdd(&colsq[gc + 1],  q1);
        }
    }
}

// colsum/colsq -> scale/shift
__global__ void bn_scale(const float* __restrict__ colsum, const float* __restrict__ colsq,
                         const float* __restrict__ gamma, const float* __restrict__ beta,
                         float* __restrict__ scale, float* __restrict__ shift) {
    int c = blockIdx.x * blockDim.x + threadIdx.x;
    float mu  = colsum[c] / (float)Nn;
    float var = colsq[c] / (float)Nn - mu * mu;
    float sc  = gamma[c] * rsqrtf(var + EPS);
    scale[c] = sc;
    shift[c] = beta[c] - mu * sc;
}

// ==================== weight transposes (+ fp16 convert) ====================
__global__ void transpose_cvt(const float* __restrict__ W, __half* __restrict__ Wt) {
    __shared__ float tile[32][33];
    int n0 = blockIdx.x * 32, k0 = blockIdx.y * 32;
    int tx = threadIdx.x, ty = threadIdx.y;
    #pragma unroll
    for (int j = 0; j < 4; j++)
        tile[ty + j * 8][tx] = W[(size_t)(k0 + ty + j * 8) * HID + (n0 + tx)];
    __syncthreads();
    #pragma unroll
    for (int j = 0; j < 4; j++)
        Wt[(size_t)(n0 + ty + j * 8) * HID + (k0 + tx)] = __float2half_rn(tile[tx][ty + j * 8]);
}

// W1 [63, 2048] -> Wt [2048 rows, 64 cols] (col 63 zero-padded)
__global__ void transpose_cvt1(const float* __restrict__ W, __half* __restrict__ Wt) {
    __shared__ float tile[32][33];
    int n0 = blockIdx.x * 32, k0 = blockIdx.y * 32;
    int tx = threadIdx.x, ty = threadIdx.y;
    #pragma unroll
    for (int j = 0; j < 4; j++) {
        int k = k0 + ty + j * 8;
        tile[ty + j * 8][tx] = (k < INF) ? W[(size_t)k * HID + (n0 + tx)] : 0.0f;
    }
    __syncthreads();
    #pragma unroll
    for (int j = 0; j < 4; j++)
        Wt[(size_t)(n0 + ty + j * 8) * K1 + (k0 + tx)] = __float2half_rn(tile[tx][ty + j * 8]);
}

// h [Nn, 63] fp32 -> h16 [Nn, 64] half (padded)
__global__ void hpad(const float* __restrict__ h, __half* __restrict__ h16) {
    int row = blockIdx.x;
    int c = threadIdx.x;
    h16[(size_t)row * K1 + c] = (c < INF) ? __float2half_rn(h[(size_t)row * INF + c]) : __half(0);
}

// ==================== graph kernels ====================
__global__ void deg_kernel(const int* __restrict__ dst, float* __restrict__ deg) {
    int i = blockIdx.x * blockDim.x + threadIdx.x;
    if (i < Ee) atomicAdd(&deg[dst[i]], 1.0f);
}

// half2 atomic scatter: out[dst[e], :] += x[src[e], :]
__global__ void scatter_add_h2(const __half* __restrict__ xh, const int* __restrict__ src,
                               const int* __restrict__ dst, __half* __restrict__ out, int F) {
    int e = blockIdx.x;
    int f2 = blockIdx.y * blockDim.x + threadIdx.x;
    if (f2 * 2 >= F) return;
    int s = src[e], d = dst[e];
    __half2 v = *((const __half2*)(xh + (size_t)s * F) + f2);
    atomicAdd((__half2*)(out + (size_t)d * F) + f2, v);
}

// BN apply + leaky relu: half in (y), half out (x).  grid: (HID/4/256, Nn)
__global__ void bn_apply_h(const __half* __restrict__ Y, __half* __restrict__ Xh,
                           const float* __restrict__ scale, const float* __restrict__ shift) {
    int row = blockIdx.y;
    int f4 = blockIdx.x * blockDim.x + threadIdx.x;
    const __half2* yp = (const __half2*)(Y + (size_t)row * HID) + f4 * 2;
    float2 a = __half22float2(yp[0]);
    float2 b = __half22float2(yp[1]);
    float4 sc = *((const float4*)scale + f4);
    float4 sh = *((const float4*)shift + f4);
    float vx = a.x * sc.x + sh.x; vx = (vx > 0.f) ? vx : SLOPE * vx;
    float vy = a.y * sc.y + sh.y; vy = (vy > 0.f) ? vy : SLOPE * vy;
    float vz = b.x * sc.z + sh.z; vz = (vz > 0.f) ? vz : SLOPE * vz;
    float vw = b.y * sc.w + sh.w; vw = (vw > 0.f) ? vw : SLOPE * vw;
    __half2* xp = (__half2*)(Xh + (size_t)row * HID) + f4 * 2;
    xp[0] = __floats2half2_rn(vx, vy);
    xp[1] = __floats2half2_rn(vz, vw);
}

// layer-3: BN apply + leaky relu + pooled atomic accumulate (half in, fp32 pool)
__global__ void bn_apply_pool(const __half* __restrict__ Y, const int* __restrict__ gid,
                              const float* __restrict__ scale, const float* __restrict__ shift,
                              float* __restrict__ hg) {
    int row = blockIdx.y;
    int f4 = blockIdx.x * blockDim.x + threadIdx.x;
    const __half2* yp = (const __half2*)(Y + (size_t)row * HID) + f4 * 2;
    float2 a = __half22float2(yp[0]);
    float2 b = __half22float2(yp[1]);
    float4 sc = *((const float4*)scale + f4);
    float4 sh = *((const float4*)shift + f4);
    float vx = a.x * sc.x + sh.x; vx = (vx > 0.f) ? vx : SLOPE * vx;
    float vy = a.y * sc.y + sh.y; vy = (vy > 0.f) ? vy : SLOPE * vy;
    float vz = b.x * sc.z + sh.z; vz = (vz > 0.f) ? vz : SLOPE * vz;
    float vw = b.y * sc.w + sh.w; vw = (vw > 0.f) ? vw : SLOPE * vw;
    int g = gid[row];
    float* dst = hg + (size_t)g * HID + f4 * 4;
    atomicAdd(dst,     vx);
    atomicAdd(dst + 1, vy);
    atomicAdd(dst + 2, vz);
    atomicAdd(dst + 3, vw);
}

// ---------------- pooling tail (fp32) ----------------
__global__ void cnt_kernel(const int* __restrict__ gid, float* __restrict__ cnt) {
    int i = blockIdx.x * blockDim.x + threadIdx.x;
    if (i < Nn) atomicAdd(&cnt[gid[i]], 1.0f);
}

__global__ void hg_div(float* __restrict__ hg, const float* __restrict__ cnt, int C) {
    int g = blockIdx.y;
    int c = blockIdx.x * blockDim.x + threadIdx.x;
    if (c >= C) return;
    hg[(size_t)g * C + c] *= 1.0f / fmaxf(cnt[g], 1.0f);
}

// ---------------- fp32 split-K head GEMM ----------------
// Y[64, Nc] += X[64, K] @ W[K, Nc] over k-slice.  grid: (Nc/128, K/128), block 256.
// Y must be zeroed first.  Weights read exactly once.
__global__ void __launch_bounds__(256, 2)
head_splitk(const float* __restrict__ X, const float* __restrict__ W,
            float* __restrict__ Y, int K, int Nc) {
    __shared__ float xs[64][129];
    int k0 = blockIdx.y * 128;
    int c0 = blockIdx.x * 128;
    int tid = threadIdx.x;
    for (int i = tid; i < 64 * 128; i += 256) {
        int r = i >> 7, k = i & 127;
        xs[r][k] = X[(size_t)r * K + k0 + k];
    }
    __syncthreads();
    int c = c0 + (tid & 127);
    int r0 = (tid >> 7) * 32;   // 0 or 32
    float acc[32];
    #pragma unroll
    for (int i = 0; i < 32; i++) acc[i] = 0.0f;
    for (int k = 0; k < 128; k++) {
        float w = W[(size_t)(k0 + k) * Nc + c];
        #pragma unroll
        for (int i = 0; i < 32; i++) acc[i] += xs[r0 + i][k] * w;
    }
    #pragma unroll
    for (int i = 0; i < 32; i++)
        atomicAdd(&Y[(size_t)(r0 + i) * Nc + c], acc[i]);
}

// bias + leaky relu over [64, Nc].  grid: (Nc/256, 64)
__global__ void bias_lrelu(float* __restrict__ Y, const float* __restrict__ b, int Nc) {
    int r = blockIdx.y;
    int c = blockIdx.x * blockDim.x + threadIdx.x;
    if (c >= Nc) return;
    float v = Y[(size_t)r * Nc + c] + b[c];
    Y[(size_t)r * Nc + c] = (v > 0.0f) ? v : SLOPE * v;
}

// tiny final GEMM (fc3)
__global__ void head_gemm(const float* __restrict__ X, const float* __restrict__ W,
                          const float* __restrict__ b, float* __restrict__ Y,
                          int K, int Nc) {
    extern __shared__ float xs2[];
    int r = blockIdx.y;
    for (int i = threadIdx.x; i < K; i += blockDim.x) xs2[i] = X[(size_t)r * K + i];
    __syncthreads();
    int c = blockIdx.x * blockDim.x + threadIdx.x;
    if (c >= Nc) return;
    float acc = 0.0f;
    for (int k = 0; k < K; k++) acc += xs2[k] * W[(size_t)k * Nc + c];
    Y[(size_t)r * Nc + c] = acc + b[c];
}

// ==================== launch ====================
extern "C" void kernel_launch(void* const* d_in, const int* in_sizes, int n_in,
                              void* d_out, int out_size) {
    (void)in_sizes; (void)n_in; (void)out_size;
    const float* h     = (const float*)d_in[0];
    const int*   src   = (const int*)  d_in[1];
    const int*   dst   = (const int*)  d_in[2];
    const int*   gid   = (const int*)  d_in[3];
    const float* Ws1   = (const float*)d_in[4];
    const float* Wn1   = (const float*)d_in[5];
    const float* b1    = (const float*)d_in[6];
    const float* Ws2   = (const float*)d_in[7];
    const float* Wn2   = (const float*)d_in[8];
    const float* b2    = (const float*)d_in[9];
    const float* Ws3   = (const float*)d_in[10];
    const float* Wn3   = (const float*)d_in[11];
    const float* b3    = (const float*)d_in[12];
    const float* g1    = (const float*)d_in[13];
    const float* be1   = (const float*)d_in[14];
    const float* g2    = (const float*)d_in[15];
    const float* be2   = (const float*)d_in[16];
    const float* g3    = (const float*)d_in[17];
    const float* be3   = (const float*)d_in[18];
    const float* fc1_w = (const float*)d_in[19];
    const float* fc1_b = (const float*)d_in[20];
    const float* fc2_w = (const float*)d_in[21];
    const float* fc2_b = (const float*)d_in[22];
    const float* fc3_w = (const float*)d_in[23];
    const float* fc3_b = (const float*)d_in[24];
    float* out = (float*)d_out;

    float *deg, *scale, *shift, *colsum, *colsq, *hg, *cnt, *t1, *t2;
    __half *nmh, *xh, *h16, *yh;
    __half *wh1s, *wh1n, *wh2s, *wh2n, *wh3s, *wh3n;
    cudaGetSymbolAddress((void**)&nmh,    g_nmh);
    cudaGetSymbolAddress((void**)&xh,     g_xh);
    cudaGetSymbolAddress((void**)&h16,    g_h16);
    cudaGetSymbolAddress((void**)&yh,     g_yh);
    cudaGetSymbolAddress((void**)&deg,    g_deg);
    cudaGetSymbolAddress((void**)&scale,  g_scale);
    cudaGetSymbolAddress((void**)&shift,  g_shift);
    cudaGetSymbolAddress((void**)&colsum, g_colsum);
    cudaGetSymbolAddress((void**)&colsq,  g_colsq);
    cudaGetSymbolAddress((void**)&hg,     g_hg);
    cudaGetSymbolAddress((void**)&cnt,    g_cnt);
    cudaGetSymbolAddress((void**)&t1,     g_t1);
    cudaGetSymbolAddress((void**)&t2,     g_t2);
    cudaGetSymbolAddress((void**)&wh1s,   g_wh1s);
    cudaGetSymbolAddress((void**)&wh1n,   g_wh1n);
    cudaGetSymbolAddress((void**)&wh2s,   g_wh2s);
    cudaGetSymbolAddress((void**)&wh2n,   g_wh2n);
    cudaGetSymbolAddress((void**)&wh3s,   g_wh3s);
    cudaGetSymbolAddress((void**)&wh3n,   g_wh3n);

    cudaFuncSetAttribute(tc_gemm_dual<K1>,  cudaFuncAttributeMaxDynamicSharedMemorySize, TCG_SMEM_BYTES);
    cudaFuncSetAttribute(tc_gemm_dual<HID>, cudaFuncAttributeMaxDynamicSharedMemorySize, TCG_SMEM_BYTES);

    cudaStream_t s = 0;

    // weight transposes (+ fp16 convert), input pad
    dim3 tblk(32, 8);
    transpose_cvt1<<<dim3(HID / 32, K1 / 32), tblk, 0, s>>>(Ws1, wh1s);
    transpose_cvt1<<<dim3(HID / 32, K1 / 32), tblk, 0, s>>>(Wn1, wh1n);
    transpose_cvt<<<dim3(HID / 32, HID / 32), tblk, 0, s>>>(Ws2, wh2s);
    transpose_cvt<<<dim3(HID / 32, HID / 32), tblk, 0, s>>>(Wn2, wh2n);
    transpose_cvt<<<dim3(HID / 32, HID / 32), tblk, 0, s>>>(Ws3, wh3s);
    transpose_cvt<<<dim3(HID / 32, HID / 32), tblk, 0, s>>>(Wn3, wh3n);
    hpad<<<Nn, K1, 0, s>>>(h, h16);

    // degrees
    cudaMemsetAsync(deg, 0, Nn * sizeof(float), s);
    deg_kernel<<<Ee / 256, 256, 0, s>>>(dst, deg);

    dim3 tc_grid(HID / 128, Nn / 128);
    dim3 ew4_grid(HID / 4 / 256, Nn);

    // ---- Layer 1 (K = 64, tensor GEMM, fused BN stats + deg-fold) ----
    cudaMemsetAsync(nmh, 0, (size_t)Nn * K1 * sizeof(__half), s);
    scatter_add_h2<<<dim3(Ee, 1), 32, 0, s>>>(h16, src, dst, nmh, K1);
    cudaMemsetAsync(colsum, 0, HID * sizeof(float), s);
    cudaMemsetAsync(colsq,  0, HID * sizeof(float), s);
    tc_gemm_dual<K1><<<tc_grid, 256, TCG_SMEM_BYTES, s>>>(nmh, wh1n, h16, wh1s, b1, deg, yh,
                                                          colsum, colsq);
    bn_scale<<<HID / 256, 256, 0, s>>>(colsum, colsq, g1, be1, scale, shift);
    bn_apply_h<<<ew4_grid, 256, 0, s>>>(yh, xh, scale, shift);

    // ---- Layer 2 ----
    cudaMemsetAsync(nmh, 0, (size_t)Nn * HID * sizeof(__half), s);
    scatter_add_h2<<<dim3(Ee, HID / 2 / 128), 128, 0, s>>>(xh, src, dst, nmh, HID);
    cudaMemsetAsync(colsum, 0, HID * sizeof(float), s);
    cudaMemsetAsync(colsq,  0, HID * sizeof(float), s);
    tc_gemm_dual<HID><<<tc_grid, 256, TCG_SMEM_BYTES, s>>>(nmh, wh2n, xh, wh2s, b2, deg, yh,
                                                           colsum, colsq);
    bn_scale<<<HID / 256, 256, 0, s>>>(colsum, colsq, g2, be2, scale, shift);
    bn_apply_h<<<ew4_grid, 256, 0, s>>>(yh, xh, scale, shift);

    // ---- Layer 3 ----
    cudaMemsetAsync(nmh, 0, (size_t)Nn * HID * sizeof(__half), s);
    scatter_add_h2<<<dim3(Ee, HID / 2 / 128), 128, 0, s>>>(xh, src, dst, nmh, HID);
    cudaMemsetAsync(colsum, 0, HID * sizeof(float), s);
    cudaMemsetAsync(colsq,  0, HID * sizeof(float), s);
    tc_gemm_dual<HID><<<tc_grid, 256, TCG_SMEM_BYTES, s>>>(nmh, wh3n, xh, wh3s, b3, deg, yh,
                                                           colsum, colsq);
    bn_scale<<<HID / 256, 256, 0, s>>>(colsum, colsq, g3, be3, scale, shift);

    // ---- Pooling (fused BN apply, fp32) ----
    cudaMemsetAsync(hg, 0, Gg * HID * sizeof(float), s);
    cudaMemsetAsync(cnt, 0, Gg * sizeof(float), s);
    cnt_kernel<<<Nn / 256, 256, 0, s>>>(gid, cnt);
    bn_apply_pool<<<ew4_grid, 256, 0, s>>>(yh, gid, scale, shift, hg);
    hg_div<<<dim3(HID / 256, Gg), 256, 0, s>>>(hg, cnt, HID);

    // ---- MLP head (fp32 split-K: weights read once, no fp16 roundings) ----
    cudaMemsetAsync(t1, 0, Gg * HID * sizeof(float), s);
    head_splitk<<<dim3(HID / 128, HID / 128), 256, 0, s>>>(hg, fc1_w, t1, HID, HID);
    bias_lrelu<<<dim3(HID / 256, Gg), 256, 0, s>>>(t1, fc1_b, HID);
    cudaMemsetAsync(t2, 0, Gg * MIDD * sizeof(float), s);
    head_splitk<<<dim3(MIDD / 128, HID / 128), 256, 0, s>>>(t1, fc2_w, t2, HID, MIDD);
    bias_lrelu<<<dim3(MIDD / 256, Gg), 256, 0, s>>>(t2, fc2_b, MIDD);
    head_gemm<<<dim3(1, Gg), 128, MIDD * sizeof(float), s>>>(t2, fc3_w, fc3_b, out, MIDD, NCLS);
}